// round 11
// baseline (speedup 1.0000x reference)
#include <cuda_runtime.h>
#include <cuda_fp16.h>
#include <math.h>
#include <stdint.h>

#define TTOK  16384      // B*S
#define DIM   1024
#define NEXP  4
#define RANK  16
#define ERCOL 64
#define LN_EPS 1e-5f
#define LO_SCALE 512.0f
#define LO_INV   (1.0f / 512.0f)

// GEMM tiling
#define BM 128
#define BN 128
#define BK 32
#define KCH   (DIM / BK)     // 32 chunks
#define ROWB  64             // row stride bytes (XOR swizzle)
#define TILEB (128 * ROWB)   // 8192 bytes per matrix tile
#define OFF_AH 0
#define OFF_AL (1 * TILEB)
#define OFF_BH (2 * TILEB)
#define OFF_BL (3 * TILEB)
#define STAGE  (4 * TILEB)   // 32768
#define NSTAGE 3
#define SMEM_TOTAL (NSTAGE * STAGE)  // 98304 -> 2 CTAs/SM

#define SWZ(row, kb) ((uint32_t)((row) * ROWB + (((kb) ^ (((row) >> 1) & 3)) << 4)))

// ---------------- scratch (static device memory) ---------------------------
__device__ float g_bufA[(size_t)TTOK * DIM];   // fp32 activations (aux/LN out)
__device__ float g_bufC[(size_t)TTOK * DIM];   // pre-LN y
__device__ float g_H[(size_t)TTOK * ERCOL];
__device__ int   g_maskbuf[TTOK];
__device__ __half g_Ah[(size_t)TTOK * DIM];    // activation hi
__device__ __half g_Al[(size_t)TTOK * DIM];    // activation lo (x512)
__device__ __half g_Bh[(size_t)TTOK * DIM];    // new_state hi
__device__ __half g_Bl[(size_t)TTOK * DIM];    // new_state lo (x512)
__device__ __half g_Wh[12ull * DIM * DIM];     // transposed weight hi [N,K]
__device__ __half g_Wl[12ull * DIM * DIM];     // transposed weight lo (x512)

// ---------------- PTX helpers ------------------------------------------------
__device__ __forceinline__ uint32_t smem_u32(const void* p) {
    uint32_t a;
    asm("{ .reg .u64 t; cvta.to.shared.u64 t, %1; cvt.u32.u64 %0, t; }" : "=r"(a) : "l"(p));
    return a;
}
#define CP_ASYNC16(dst, src) \
    asm volatile("cp.async.cg.shared.global [%0], [%1], 16;" :: "r"(dst), "l"(src) : "memory")
#define CP_COMMIT() asm volatile("cp.async.commit_group;" ::: "memory")
#define CP_WAIT0()  asm volatile("cp.async.wait_group 0;" ::: "memory")
#define CP_WAIT1()  asm volatile("cp.async.wait_group 1;" ::: "memory")
#define LDSM_X4(r0, r1, r2, r3, addr) \
    asm volatile("ldmatrix.sync.aligned.m8n8.x4.shared.b16 {%0,%1,%2,%3}, [%4];" \
                 : "=r"(r0), "=r"(r1), "=r"(r2), "=r"(r3) : "r"(addr))

// fp16 inputs, fp32 accumulate
__device__ __forceinline__ void mma_f32acc(float* d, const uint32_t* a, const uint32_t* b) {
    asm volatile(
        "mma.sync.aligned.m16n8k16.row.col.f32.f16.f16.f32 "
        "{%0,%1,%2,%3},{%4,%5,%6,%7},{%8,%9},{%0,%1,%2,%3};"
        : "+f"(d[0]), "+f"(d[1]), "+f"(d[2]), "+f"(d[3])
        : "r"(a[0]), "r"(a[1]), "r"(a[2]), "r"(a[3]), "r"(b[0]), "r"(b[1]));
}
// fp16 inputs, fp16 accumulate (hoped 2x rate)
__device__ __forceinline__ void mma_f16acc(uint32_t* d, const uint32_t* a, const uint32_t* b) {
    asm volatile(
        "mma.sync.aligned.m16n8k16.row.col.f16.f16.f16.f16 "
        "{%0,%1},{%2,%3,%4,%5},{%6,%7},{%0,%1};"
        : "+r"(d[0]), "+r"(d[1])
        : "r"(a[0]), "r"(a[1]), "r"(a[2]), "r"(a[3]), "r"(b[0]), "r"(b[1]));
}

__device__ __forceinline__ uint32_t pack_h2(float a, float b) {
    __half2 h = __floats2half2_rn(a, b);
    return *(uint32_t*)&h;
}
// hi/lo fp16 split with scaled lo
__device__ __forceinline__ void hsplit(float x, float& h, float& l) {
    __half hh = __float2half_rn(x);
    h = __half2float(hh);
    l = (x - h) * LO_SCALE;
}

// ---------------------------------------------------------------------------
// Input split: X fp32 -> fp16 hi + scaled lo
// ---------------------------------------------------------------------------
__global__ __launch_bounds__(256) void split_x(
    const float* __restrict__ X, __half* __restrict__ H, __half* __restrict__ L)
{
    const size_t i = ((size_t)blockIdx.x * 256 + threadIdx.x) * 4;
    float4 v = *(const float4*)&X[i];
    float h0, l0, h1, l1, h2, l2, h3, l3;
    hsplit(v.x, h0, l0); hsplit(v.y, h1, l1);
    hsplit(v.z, h2, l2); hsplit(v.w, h3, l3);
    *(uint2*)&H[i] = make_uint2(pack_h2(v.x, v.y), pack_h2(v.z, v.w));
    *(uint2*)&L[i] = make_uint2(pack_h2(l0, l1), pack_h2(l2, l3));
}

// ---------------------------------------------------------------------------
// Weight transpose + fp16 hi/lo split for ALL 12 matrices in one launch.
// ---------------------------------------------------------------------------
__global__ __launch_bounds__(256) void wsplit_all(
    const float* __restrict__ Wi0, const float* __restrict__ Wo0,
    const float* __restrict__ Wi1, const float* __restrict__ Wo1,
    __half* __restrict__ Wh, __half* __restrict__ Wl)
{
    __shared__ float t[32][33];
    const int z   = blockIdx.z;
    const int grp = z / 3;
    const int l   = z % 3;
    const float* src = (grp == 0) ? Wi0 : (grp == 1) ? Wo0 : (grp == 2) ? Wi1 : Wo1;
    const float* Wm = src + (size_t)l * DIM * DIM;
    __half* Whm = Wh + (size_t)z * DIM * DIM;
    __half* Wlm = Wl + (size_t)z * DIM * DIM;
    const int n0 = blockIdx.x * 32, k0 = blockIdx.y * 32;
    const int tx = threadIdx.x & 31, ty = threadIdx.x >> 5;
    #pragma unroll
    for (int i = 0; i < 4; i++)
        t[ty + i * 8][tx] = Wm[(size_t)(k0 + ty + i * 8) * DIM + n0 + tx];
    __syncthreads();
    #pragma unroll
    for (int i = 0; i < 4; i++) {
        float v = t[tx][ty + i * 8];
        float h, lo; hsplit(v, h, lo);
        size_t o = (size_t)(n0 + ty + i * 8) * DIM + k0 + tx;
        Whm[o] = __float2half_rn(h); Wlm[o] = __float2half_rn(lo);
    }
}

// ---------------------------------------------------------------------------
// fp16-split GEMM: hh with f32-acc, (hl + lh) with f16-acc (shared).
//   MODE 0: o = sigmoid(acc + bias) * aux * td  -> fp16 hi/lo (Ch/Cl)
//   MODE 1: o = acc + bias + aux                -> fp32 (C)
// CTA 128x128, 512 threads, 16 warps (4x4), warp tile 32x32, 3-stage.
// ---------------------------------------------------------------------------
template<int MODE>
__global__ __launch_bounds__(512, 2) void gemm_mma(
    const __half* __restrict__ Ah, const __half* __restrict__ Al,
    const __half* __restrict__ Wh, const __half* __restrict__ Wl,
    const float* __restrict__ bias, const float* __restrict__ aux,
    const float* __restrict__ td, float* __restrict__ C,
    __half* __restrict__ Ch, __half* __restrict__ Cl)
{
    extern __shared__ char smem[];
    const uint32_t sb0 = smem_u32(smem);
    const int tid  = threadIdx.x;
    const int lane = tid & 31;
    const int wid  = tid >> 5;
    const int m0 = blockIdx.y * BM;
    const int n0 = blockIdx.x * BN;
    const int wm0 = (wid >> 2) * 32;
    const int wn0 = (wid & 3) * 32;

    float hh[2][4][4];
    uint32_t cr[2][4][2];
    #pragma unroll
    for (int mt = 0; mt < 2; mt++)
        #pragma unroll
        for (int nt = 0; nt < 4; nt++) {
            #pragma unroll
            for (int j = 0; j < 4; j++) hh[mt][nt][j] = 0.f;
            cr[mt][nt][0] = 0u; cr[mt][nt][1] = 0u;
        }

    // load slots: 512 threads, 1 x 16B per tile per thread
    const int rowL = tid >> 2, kbL = tid & 3;
    const uint32_t soL = SWZ(rowL, kbL);

    auto load_chunk = [&](int c, int st) {
        const int k0c = c * BK;
        const uint32_t sbn = sb0 + st * STAGE;
        const size_t ga = (size_t)(m0 + rowL) * DIM + k0c + kbL * 8;
        const size_t gb = (size_t)(n0 + rowL) * DIM + k0c + kbL * 8;
        CP_ASYNC16(sbn + OFF_AH + soL, Ah + ga);
        CP_ASYNC16(sbn + OFF_AL + soL, Al + ga);
        CP_ASYNC16(sbn + OFF_BH + soL, Wh + gb);
        CP_ASYNC16(sbn + OFF_BL + soL, Wl + gb);
        CP_COMMIT();
    };

    load_chunk(0, 0);
    load_chunk(1, 1);
    CP_WAIT1();
    __syncthreads();

    const int qr = lane >> 3;
    const int rr = lane & 7;

    int st = 0;
    for (int c = 0; c < KCH; c++) {
        const uint32_t sbst = sb0 + st * STAGE;
        const int stp2 = (st + 2 >= NSTAGE) ? st + 2 - NSTAGE : st + 2;
        const bool more = (c + 2 < KCH);
        if (more) load_chunk(c + 2, stp2);

        #pragma unroll
        for (int kk = 0; kk < 2; kk++) {
            uint32_t ah[2][4], al[2][4], bh[4][2], bl[4][2];
            #pragma unroll
            for (int mt = 0; mt < 2; mt++) {
                int arow = wm0 + mt * 16 + rr + (qr & 1) * 8;
                int akb  = kk * 2 + (qr >> 1);
                uint32_t aoff = SWZ(arow, akb);
                LDSM_X4(ah[mt][0], ah[mt][1], ah[mt][2], ah[mt][3], sbst + OFF_AH + aoff);
                LDSM_X4(al[mt][0], al[mt][1], al[mt][2], al[mt][3], sbst + OFF_AL + aoff);
            }
            #pragma unroll
            for (int ng = 0; ng < 2; ng++) {
                int brow = wn0 + ng * 16 + rr + (qr >> 1) * 8;
                int bkb  = kk * 2 + (qr & 1);
                uint32_t boff = SWZ(brow, bkb);
                uint32_t t0, t1, t2, t3;
                LDSM_X4(t0, t1, t2, t3, sbst + OFF_BH + boff);
                bh[ng * 2][0] = t0; bh[ng * 2][1] = t1;
                bh[ng * 2 + 1][0] = t2; bh[ng * 2 + 1][1] = t3;
                LDSM_X4(t0, t1, t2, t3, sbst + OFF_BL + boff);
                bl[ng * 2][0] = t0; bl[ng * 2][1] = t1;
                bl[ng * 2 + 1][0] = t2; bl[ng * 2 + 1][1] = t3;
            }
            // hh pass (f32 acc)
            #pragma unroll
            for (int mt = 0; mt < 2; mt++)
                #pragma unroll
                for (int nt = 0; nt < 4; nt++)
                    mma_f32acc(hh[mt][nt], ah[mt], bh[nt]);
            // cross passes (f16 acc, shared accumulator, both scaled x512)
            #pragma unroll
            for (int mt = 0; mt < 2; mt++)
                #pragma unroll
                for (int nt = 0; nt < 4; nt++)
                    mma_f16acc(cr[mt][nt], ah[mt], bl[nt]);
            #pragma unroll
            for (int mt = 0; mt < 2; mt++)
                #pragma unroll
                for (int nt = 0; nt < 4; nt++)
                    mma_f16acc(cr[mt][nt], al[mt], bh[nt]);
        }

        if (more) CP_WAIT1();
        else      CP_WAIT0();
        __syncthreads();
        st = (st + 1 >= NSTAGE) ? 0 : st + 1;
    }

    // -------- epilogue --------
    const int r4 = lane >> 2;
    const int c2 = (lane & 3) * 2;
    #pragma unroll
    for (int mt = 0; mt < 2; mt++) {
        const int rowb = m0 + wm0 + mt * 16 + r4;
        #pragma unroll
        for (int nt = 0; nt < 4; nt++) {
            const int col = n0 + wn0 + nt * 8 + c2;
            float2 bi = *(const float2*)&bias[col];
            float2 tdv;
            if (MODE == 0) tdv = *(const float2*)&td[col];
            #pragma unroll
            for (int half = 0; half < 2; half++) {
                const int rw = rowb + half * 8;
                float2 ax = *(const float2*)&aux[(size_t)rw * DIM + col];
                __half2 crh = *(__half2*)&cr[mt][nt][half];
                float2 crf = __half22float2(crh);
                float v0 = hh[mt][nt][half * 2 + 0] + crf.x * LO_INV + bi.x;
                float v1 = hh[mt][nt][half * 2 + 1] + crf.y * LO_INV + bi.y;
                if (MODE == 0) {
                    float g0 = 1.0f / (1.0f + expf(-v0));
                    float g1 = 1.0f / (1.0f + expf(-v1));
                    float o0 = g0 * ax.x * tdv.x;
                    float o1 = g1 * ax.y * tdv.y;
                    float h0, l0, h1, l1;
                    hsplit(o0, h0, l0); hsplit(o1, h1, l1);
                    *(uint32_t*)&Ch[(size_t)rw * DIM + col] = pack_h2(o0, o1);
                    *(uint32_t*)&Cl[(size_t)rw * DIM + col] = pack_h2(l0, l1);
                } else {
                    float2 o = make_float2(v0 + ax.x, v1 + ax.y);
                    *(float2*)&C[(size_t)rw * DIM + col] = o;
                }
            }
        }
    }
}

// ---------------------------------------------------------------------------
// Row LayerNorm: fp32 out + fp16 hi/lo out
// ---------------------------------------------------------------------------
__global__ __launch_bounds__(256) void ln_kernel(
    const float* __restrict__ Y, const float* __restrict__ g,
    const float* __restrict__ beta, float* __restrict__ O,
    __half* __restrict__ Oh, __half* __restrict__ Ol)
{
    const int row = blockIdx.x;
    const int tid = threadIdx.x;
    float4 v = *(const float4*)&Y[(size_t)row * DIM + tid * 4];
    float s  = v.x + v.y + v.z + v.w;
    float ss = v.x * v.x + v.y * v.y + v.z * v.z + v.w * v.w;

    __shared__ float rs[8], rss[8];
    #pragma unroll
    for (int o = 16; o > 0; o >>= 1) {
        s  += __shfl_down_sync(0xffffffffu, s,  o);
        ss += __shfl_down_sync(0xffffffffu, ss, o);
    }
    if ((tid & 31) == 0) { rs[tid >> 5] = s; rss[tid >> 5] = ss; }
    __syncthreads();
    float ts = 0.f, tss = 0.f;
    #pragma unroll
    for (int w = 0; w < 8; w++) { ts += rs[w]; tss += rss[w]; }
    float mu   = ts * (1.0f / DIM);
    float var  = tss * (1.0f / DIM) - mu * mu;
    float rstd = rsqrtf(var + LN_EPS);

    float4 g4 = *(const float4*)&g[tid * 4];
    float4 b4 = *(const float4*)&beta[tid * 4];
    float4 o4;
    o4.x = (v.x - mu) * rstd * g4.x + b4.x;
    o4.y = (v.y - mu) * rstd * g4.y + b4.y;
    o4.z = (v.z - mu) * rstd * g4.z + b4.z;
    o4.w = (v.w - mu) * rstd * g4.w + b4.w;
    const size_t base = (size_t)row * DIM + tid * 4;
    *(float4*)&O[base] = o4;
    float h0, l0, h1, l1, h2, l2, h3, l3;
    hsplit(o4.x, h0, l0); hsplit(o4.y, h1, l1);
    hsplit(o4.z, h2, l2); hsplit(o4.w, h3, l3);
    *(uint2*)&Oh[base] = make_uint2(pack_h2(o4.x, o4.y), pack_h2(o4.z, o4.w));
    *(uint2*)&Ol[base] = make_uint2(pack_h2(l0, l1), pack_h2(l2, l3));
}

// ---------------------------------------------------------------------------
// Gate softmax + top-2 mask
// ---------------------------------------------------------------------------
__global__ __launch_bounds__(128) void gate_kernel(
    const float* __restrict__ Z, const float* __restrict__ W,
    const float* __restrict__ b, float* __restrict__ probs_out,
    int* __restrict__ mask_out)
{
    const int t   = blockIdx.x;
    const int tid = threadIdx.x;
    const float* z = Z + (size_t)t * DIM;
    float4 acc = make_float4(0.f, 0.f, 0.f, 0.f);
    for (int d = tid; d < DIM; d += 128) {
        float zv = z[d];
        float4 w = *(const float4*)&W[d * 4];
        acc.x = fmaf(zv, w.x, acc.x);
        acc.y = fmaf(zv, w.y, acc.y);
        acc.z = fmaf(zv, w.z, acc.z);
        acc.w = fmaf(zv, w.w, acc.w);
    }
    __shared__ float4 red[128];
    red[tid] = acc;
    __syncthreads();
    for (int s = 64; s > 0; s >>= 1) {
        if (tid < s) {
            float4 o = red[tid + s];
            red[tid].x += o.x; red[tid].y += o.y;
            red[tid].z += o.z; red[tid].w += o.w;
        }
        __syncthreads();
    }
    if (tid == 0) {
        float l[4] = { red[0].x + b[0], red[0].y + b[1],
                       red[0].z + b[2], red[0].w + b[3] };
        float mx = l[0];
        #pragma unroll
        for (int e = 1; e < 4; e++) mx = fmaxf(mx, l[e]);
        float ex[4], sum = 0.f;
        #pragma unroll
        for (int e = 0; e < 4; e++) { ex[e] = expf(l[e] - mx); sum += ex[e]; }
        float inv = 1.0f / sum;
        #pragma unroll
        for (int e = 0; e < 4; e++) probs_out[(size_t)t * 4 + e] = ex[e] * inv;
        int i1 = 0;
        #pragma unroll
        for (int e = 1; e < 4; e++) if (l[e] > l[i1]) i1 = e;
        int i2 = -1;
        #pragma unroll
        for (int e = 0; e < 4; e++) {
            if (e == i1) continue;
            if (i2 < 0 || l[e] > l[i2]) i2 = e;
        }
        mask_out[t] = (1 << i1) | (1 << i2);
    }
}

// ---------------------------------------------------------------------------
// H = mask * gelu(Z @ Aflat)
// ---------------------------------------------------------------------------
__global__ __launch_bounds__(256) void h_kernel(
    const float* __restrict__ Z, const float* __restrict__ loraA,
    const int* __restrict__ mask, float* __restrict__ H)
{
    __shared__ float Zs[16][68];
    __shared__ float Afs[16][64];

    const int m0  = blockIdx.x * 64;
    const int tid = threadIdx.x;
    const int ty  = tid >> 4;
    const int tx  = tid & 15;

    float acc[4][4];
    #pragma unroll
    for (int i = 0; i < 4; i++)
        #pragma unroll
        for (int j = 0; j < 4; j++) acc[i][j] = 0.f;

    for (int k0 = 0; k0 < DIM; k0 += 16) {
        {
            int row = tid >> 2;
            int kq  = (tid & 3) << 2;
            float4 v = *(const float4*)&Z[(size_t)(m0 + row) * DIM + k0 + kq];
            Zs[kq + 0][row] = v.x; Zs[kq + 1][row] = v.y;
            Zs[kq + 2][row] = v.z; Zs[kq + 3][row] = v.w;
        }
        {
            int k  = tid >> 4;
            int c4 = (tid & 15) << 2;
            int e  = c4 >> 4;
            int r  = c4 & 15;
            float4 v = *(const float4*)&loraA[(size_t)e * DIM * RANK + (size_t)(k0 + k) * RANK + r];
            *(float4*)&Afs[k][c4] = v;
        }
        __syncthreads();
        #pragma unroll
        for (int k = 0; k < 16; k++) {
            float a[4], b[4];
            *(float4*)&a[0] = *(float4*)&Zs[k][ty * 4];
            *(float4*)&b[0] = *(float4*)&Afs[k][tx * 4];
            #pragma unroll
            for (int i = 0; i < 4; i++)
                #pragma unroll
                for (int j = 0; j < 4; j++)
                    acc[i][j] = fmaf(a[i], b[j], acc[i][j]);
        }
        __syncthreads();
    }

    #pragma unroll
    for (int i = 0; i < 4; i++) {
        int m  = m0 + ty * 4 + i;
        int mk = mask[m];
        #pragma unroll
        for (int j = 0; j < 4; j++) {
            int c = tx * 4 + j;
            int e = c >> 4;
            float x = acc[i][j];
            float h = 0.5f * x * (1.0f + erff(x * 0.70710678118654752f));
            H[(size_t)m * ERCOL + c] = ((mk >> e) & 1) ? h : 0.0f;
        }
    }
}

// ---------------------------------------------------------------------------
// pred = H @ Bflat
// ---------------------------------------------------------------------------
__global__ __launch_bounds__(256) void combine_kernel(
    const float* __restrict__ H, const float* __restrict__ Bf,
    float* __restrict__ O)
{
    const int d  = blockIdx.y * 256 + threadIdx.x;
    const int t0 = blockIdx.x * 16;
    __shared__ float hs[16][64];
    {
        int row = threadIdx.x >> 4;
        int c   = (threadIdx.x & 15) << 2;
        *(float4*)&hs[row][c] = *(const float4*)&H[(size_t)(t0 + row) * ERCOL + c];
    }
    __syncthreads();
    float acc[16];
    #pragma unroll
    for (int i = 0; i < 16; i++) acc[i] = 0.f;
    #pragma unroll 4
    for (int c = 0; c < 64; c++) {
        float bv = Bf[(size_t)c * DIM + d];
        #pragma unroll
        for (int i = 0; i < 16; i++) acc[i] = fmaf(hs[i][c], bv, acc[i]);
    }
    #pragma unroll
    for (int i = 0; i < 16; i++) O[(size_t)(t0 + i) * DIM + d] = acc[i];
}

// ---------------------------------------------------------------------------
extern "C" void kernel_launch(void* const* d_in, const int* in_sizes, int n_in,
                              void* d_out, int out_size)
{
    const float* x_ctx  = (const float*)d_in[0];
    const float* x_tgt  = (const float*)d_in[1];
    const float* P[2][7];
    for (int i = 0; i < 7; i++) { P[0][i] = (const float*)d_in[2 + i];
                                  P[1][i] = (const float*)d_in[9 + i]; }
    const float* gate_W = (const float*)d_in[16];
    const float* gate_b = (const float*)d_in[17];
    const float* lora_A = (const float*)d_in[18];
    const float* lora_B = (const float*)d_in[19];

    float* out      = (float*)d_out;
    float* out_pred = out;
    float* out_gate = out + (size_t)TTOK * DIM;
    float* out_ztgt = out_gate + (size_t)TTOK * NEXP;

    float *bufA, *bufC, *bufH; int* bufM;
    __half *Ah, *Al, *Bh, *Bl, *Wh, *Wl;
    cudaGetSymbolAddress((void**)&bufA, g_bufA);
    cudaGetSymbolAddress((void**)&bufC, g_bufC);
    cudaGetSymbolAddress((void**)&bufH, g_H);
    cudaGetSymbolAddress((void**)&Ah,   g_Ah);
    cudaGetSymbolAddress((void**)&Al,   g_Al);
    cudaGetSymbolAddress((void**)&Bh,   g_Bh);
    cudaGetSymbolAddress((void**)&Bl,   g_Bl);
    cudaGetSymbolAddress((void**)&Wh,   g_Wh);
    cudaGetSymbolAddress((void**)&Wl,   g_Wl);
    cudaGetSymbolAddress((void**)&bufM, g_maskbuf);

    cudaFuncSetAttribute(gemm_mma<0>, cudaFuncAttributeMaxDynamicSharedMemorySize, SMEM_TOTAL);
    cudaFuncSetAttribute(gemm_mma<1>, cudaFuncAttributeMaxDynamicSharedMemorySize, SMEM_TOTAL);

    const size_t MM = (size_t)DIM * DIM;
    wsplit_all<<<dim3(32, 32, 12), 256>>>(P[0][0], P[0][3], P[1][0], P[1][3], Wh, Wl);

    const dim3 gg(DIM / BN, TTOK / BM);   // (8, 128)
    const int splitGrid = (TTOK * DIM) / 1024;

    for (int s = 0; s < 2; s++) {
        const float* bi   = P[s][1];
        const float* td   = P[s][2];
        const float* bo   = P[s][4];
        const float* gam  = P[s][5];
        const float* beta = P[s][6];
        const float* xin  = s ? x_tgt : x_ctx;

        split_x<<<splitGrid, 256>>>(xin, Ah, Al);

        for (int l = 0; l < 3; l++) {
            const float* X = (l == 0) ? xin : bufA;
            const size_t wiOff = (size_t)(s * 6 + l) * MM;
            const size_t woOff = (size_t)(s * 6 + 3 + l) * MM;
            gemm_mma<0><<<gg, 512, SMEM_TOTAL>>>(Ah, Al, Wh + wiOff, Wl + wiOff,
                                                 bi + l * DIM, X, td + l * DIM,
                                                 nullptr, Bh, Bl);
            gemm_mma<1><<<gg, 512, SMEM_TOTAL>>>(Bh, Bl, Wh + woOff, Wl + woOff,
                                                 bo + l * DIM, X, nullptr,
                                                 bufC, nullptr, nullptr);
            float* dst = (s == 1 && l == 2) ? out_ztgt : bufA;
            ln_kernel<<<TTOK, 256>>>(bufC, gam + l * DIM, beta + l * DIM, dst, Ah, Al);
        }
        if (s == 0) {
            gate_kernel<<<TTOK, 128>>>(bufA, gate_W, gate_b, out_gate, bufM);
            h_kernel<<<TTOK / 64, 256>>>(bufA, lora_A, bufM, bufH);
            combine_kernel<<<dim3(TTOK / 16, DIM / 256), 256>>>(bufH, lora_B, out_pred);
        }
    }
}

// round 12
// speedup vs baseline: 1.2066x; 1.2066x over previous
#include <cuda_runtime.h>
#include <cuda_bf16.h>
#include <math.h>
#include <stdint.h>

#define TTOK  16384      // B*S per stack
#define TTOK2 32768      // both stacks
#define DIM   1024
#define NEXP  4
#define RANK  16
#define ERCOL 64
#define LN_EPS 1e-5f

// GEMM tiling (R9 core)
#define BM 128
#define BN 128
#define BK 32
#define KCH   (DIM / BK)     // 32 chunks
#define ROWB  64
#define TILEB (128 * ROWB)   // 8192
#define OFF_AH 0
#define OFF_AL (1 * TILEB)
#define OFF_BH (2 * TILEB)
#define OFF_BL (3 * TILEB)
#define STAGE  (4 * TILEB)   // 32768
#define NSTAGE 3
#define SMEM_TOTAL (NSTAGE * STAGE)  // 98304 -> 2 CTAs/SM

#define SWZ(row, kb) ((uint32_t)((row) * ROWB + (((kb) ^ (((row) >> 1) & 3)) << 4)))

// ---------------- scratch (static device memory; sized for BOTH stacks) ----
__device__ float g_bufA[(size_t)TTOK2 * DIM];   // fp32 LN out (both stacks)
__device__ float g_bufC[(size_t)TTOK2 * DIM];   // pre-LN y
__device__ float g_H[(size_t)TTOK * ERCOL];
__device__ int   g_maskbuf[TTOK];
__device__ __nv_bfloat16 g_Ah[(size_t)TTOK2 * DIM];
__device__ __nv_bfloat16 g_Al[(size_t)TTOK2 * DIM];
__device__ __nv_bfloat16 g_Bh[(size_t)TTOK2 * DIM];
__device__ __nv_bfloat16 g_Bl[(size_t)TTOK2 * DIM];
__device__ __nv_bfloat16 g_Wh[12ull * DIM * DIM];
__device__ __nv_bfloat16 g_Wl[12ull * DIM * DIM];

// ---------------- PTX helpers ------------------------------------------------
__device__ __forceinline__ uint32_t smem_u32(const void* p) {
    uint32_t a;
    asm("{ .reg .u64 t; cvta.to.shared.u64 t, %1; cvt.u32.u64 %0, t; }" : "=r"(a) : "l"(p));
    return a;
}
#define CP_ASYNC16(dst, src) \
    asm volatile("cp.async.cg.shared.global [%0], [%1], 16;" :: "r"(dst), "l"(src) : "memory")
#define CP_COMMIT() asm volatile("cp.async.commit_group;" ::: "memory")
#define CP_WAIT0()  asm volatile("cp.async.wait_group 0;" ::: "memory")
#define CP_WAIT1()  asm volatile("cp.async.wait_group 1;" ::: "memory")
#define LDSM_X4(r0, r1, r2, r3, addr) \
    asm volatile("ldmatrix.sync.aligned.m8n8.x4.shared.b16 {%0,%1,%2,%3}, [%4];" \
                 : "=r"(r0), "=r"(r1), "=r"(r2), "=r"(r3) : "r"(addr))

__device__ __forceinline__ void mma_bf16(float* d, const uint32_t* a, const uint32_t* b) {
    asm volatile(
        "mma.sync.aligned.m16n8k16.row.col.f32.bf16.bf16.f32 "
        "{%0,%1,%2,%3}, {%4,%5,%6,%7}, {%8,%9}, {%0,%1,%2,%3};"
        : "+f"(d[0]), "+f"(d[1]), "+f"(d[2]), "+f"(d[3])
        : "r"(a[0]), "r"(a[1]), "r"(a[2]), "r"(a[3]), "r"(b[0]), "r"(b[1]));
}

__device__ __forceinline__ uint32_t pack_bf16x2(float a, float b) {
    __nv_bfloat16 h0 = __float2bfloat16(a);
    __nv_bfloat16 h1 = __float2bfloat16(b);
    return (uint32_t)__bfloat16_as_ushort(h0) | ((uint32_t)__bfloat16_as_ushort(h1) << 16);
}

// ---------------------------------------------------------------------------
// Input split: X fp32 -> bf16 hi/lo (writes at row offset)
// ---------------------------------------------------------------------------
__global__ __launch_bounds__(256) void split_x(
    const float* __restrict__ X, __nv_bfloat16* __restrict__ H,
    __nv_bfloat16* __restrict__ L)
{
    const size_t i = ((size_t)blockIdx.x * 256 + threadIdx.x) * 4;
    float4 v = *(const float4*)&X[i];
    float hx = __bfloat162float(__float2bfloat16(v.x));
    float hy = __bfloat162float(__float2bfloat16(v.y));
    float hz = __bfloat162float(__float2bfloat16(v.z));
    float hw = __bfloat162float(__float2bfloat16(v.w));
    *(uint2*)&H[i] = make_uint2(pack_bf16x2(v.x, v.y), pack_bf16x2(v.z, v.w));
    *(uint2*)&L[i] = make_uint2(pack_bf16x2(v.x - hx, v.y - hy),
                                pack_bf16x2(v.z - hz, v.w - hw));
}

// ---------------------------------------------------------------------------
// Weight transpose + bf16 hi/lo split for all 12 matrices.
// slots: [Wi(s0) l | Wo(s0) l | Wi(s1) l | Wo(s1) l]
// ---------------------------------------------------------------------------
__global__ __launch_bounds__(256) void wsplit_all(
    const float* __restrict__ Wi0, const float* __restrict__ Wo0,
    const float* __restrict__ Wi1, const float* __restrict__ Wo1,
    __nv_bfloat16* __restrict__ Wh, __nv_bfloat16* __restrict__ Wl)
{
    __shared__ float t[32][33];
    const int z   = blockIdx.z;
    const int grp = z / 3;
    const int l   = z % 3;
    const float* src = (grp == 0) ? Wi0 : (grp == 1) ? Wo0 : (grp == 2) ? Wi1 : Wo1;
    const float* Wm = src + (size_t)l * DIM * DIM;
    __nv_bfloat16* Whm = Wh + (size_t)z * DIM * DIM;
    __nv_bfloat16* Wlm = Wl + (size_t)z * DIM * DIM;
    const int n0 = blockIdx.x * 32, k0 = blockIdx.y * 32;
    const int tx = threadIdx.x & 31, ty = threadIdx.x >> 5;
    #pragma unroll
    for (int i = 0; i < 4; i++)
        t[ty + i * 8][tx] = Wm[(size_t)(k0 + ty + i * 8) * DIM + n0 + tx];
    __syncthreads();
    #pragma unroll
    for (int i = 0; i < 4; i++) {
        float v = t[tx][ty + i * 8];
        __nv_bfloat16 h = __float2bfloat16(v);
        __nv_bfloat16 lo = __float2bfloat16(v - __bfloat162float(h));
        size_t o = (size_t)(n0 + ty + i * 8) * DIM + k0 + tx;
        Whm[o] = h; Wlm[o] = lo;
    }
}

// ---------------------------------------------------------------------------
// 3xBF16 split GEMM, BATCHED over both stacks (M = 32768).
// Tiles with m0 >= TTOK use the tgt-stack weight slot / bias / td / aux.
//   MODE 0: o = sigmoid(acc + bias) * aux * td  -> bf16 hi/lo (Ch/Cl)
//   MODE 1: o = acc + bias + aux                -> fp32 (C)
// CTA 128x128, BK=32, 8 warps (2x4), warp tile 64x32, 3-stage, 2 CTAs/SM.
// ---------------------------------------------------------------------------
template<int MODE>
__global__ __launch_bounds__(256, 2) void gemm_mma(
    const __nv_bfloat16* __restrict__ Ah, const __nv_bfloat16* __restrict__ Al,
    const __nv_bfloat16* __restrict__ WhBase, const __nv_bfloat16* __restrict__ WlBase,
    int slotE, int slotT,
    const float* __restrict__ bias_e, const float* __restrict__ bias_t,
    const float* __restrict__ aux_e,  const float* __restrict__ aux_t,
    const float* __restrict__ td_e,   const float* __restrict__ td_t,
    float* __restrict__ C, __nv_bfloat16* __restrict__ Ch, __nv_bfloat16* __restrict__ Cl)
{
    extern __shared__ char smem[];
    const uint32_t sb0 = smem_u32(smem);
    const int tid  = threadIdx.x;
    const int lane = tid & 31;
    const int wid  = tid >> 5;
    const int m0 = blockIdx.y * BM;
    const int n0 = blockIdx.x * BN;
    const int stk = (m0 >= TTOK);
    const size_t MM = (size_t)DIM * DIM;
    const __nv_bfloat16* Wh = WhBase + (size_t)(stk ? slotT : slotE) * MM;
    const __nv_bfloat16* Wl = WlBase + (size_t)(stk ? slotT : slotE) * MM;
    const float* bias = stk ? bias_t : bias_e;
    const float* aux  = stk ? aux_t  : aux_e;
    const float* td   = stk ? td_t   : td_e;
    const int auxOff  = stk ? TTOK : 0;     // aux is indexed per-stack

    const int wm0 = (wid >> 2) * 64;
    const int wn0 = (wid & 3) * 32;

    float acc[4][4][4];
    #pragma unroll
    for (int mt = 0; mt < 4; mt++)
        #pragma unroll
        for (int nt = 0; nt < 4; nt++)
            #pragma unroll
            for (int j = 0; j < 4; j++) acc[mt][nt][j] = 0.f;

    const int row0 = tid & 127, kb0 = tid >> 7;
    const int kb1  = kb0 + 2;
    const uint32_t so0 = SWZ(row0, kb0);
    const uint32_t so1 = SWZ(row0, kb1);

    auto load_chunk = [&](int c, int st) {
        const int k0c = c * BK;
        const uint32_t sbn = sb0 + st * STAGE;
        {
            const size_t ga = (size_t)(m0 + row0) * DIM + k0c + kb0 * 8;
            const size_t gb = (size_t)(n0 + row0) * DIM + k0c + kb0 * 8;
            CP_ASYNC16(sbn + OFF_AH + so0, Ah + ga);
            CP_ASYNC16(sbn + OFF_AL + so0, Al + ga);
            CP_ASYNC16(sbn + OFF_BH + so0, Wh + gb);
            CP_ASYNC16(sbn + OFF_BL + so0, Wl + gb);
        }
        {
            const size_t ga = (size_t)(m0 + row0) * DIM + k0c + kb1 * 8;
            const size_t gb = (size_t)(n0 + row0) * DIM + k0c + kb1 * 8;
            CP_ASYNC16(sbn + OFF_AH + so1, Ah + ga);
            CP_ASYNC16(sbn + OFF_AL + so1, Al + ga);
            CP_ASYNC16(sbn + OFF_BH + so1, Wh + gb);
            CP_ASYNC16(sbn + OFF_BL + so1, Wl + gb);
        }
        CP_COMMIT();
    };

    load_chunk(0, 0);
    load_chunk(1, 1);
    CP_WAIT1();
    __syncthreads();

    const int qr = lane >> 3;
    const int rr = lane & 7;

    int st = 0;
    for (int c = 0; c < KCH; c++) {
        const uint32_t sbst = sb0 + st * STAGE;
        const int stp2 = (st + 2 >= NSTAGE) ? st + 2 - NSTAGE : st + 2;
        const bool more = (c + 2 < KCH);
        if (more) load_chunk(c + 2, stp2);

        #pragma unroll
        for (int kk = 0; kk < 2; kk++) {
            uint32_t bh[4][2], bl[4][2];
            #pragma unroll
            for (int ng = 0; ng < 2; ng++) {
                int brow = wn0 + ng * 16 + rr + (qr >> 1) * 8;
                int bkb  = kk * 2 + (qr & 1);
                uint32_t boff = SWZ(brow, bkb);
                uint32_t t0, t1, t2, t3;
                LDSM_X4(t0, t1, t2, t3, sbst + OFF_BH + boff);
                bh[ng * 2][0] = t0; bh[ng * 2][1] = t1;
                bh[ng * 2 + 1][0] = t2; bh[ng * 2 + 1][1] = t3;
                LDSM_X4(t0, t1, t2, t3, sbst + OFF_BL + boff);
                bl[ng * 2][0] = t0; bl[ng * 2][1] = t1;
                bl[ng * 2 + 1][0] = t2; bl[ng * 2 + 1][1] = t3;
            }
            #pragma unroll
            for (int mt = 0; mt < 4; mt++) {
                uint32_t ahf[4], alf[4];
                int arow = wm0 + mt * 16 + rr + (qr & 1) * 8;
                int akb  = kk * 2 + (qr >> 1);
                uint32_t aoff = SWZ(arow, akb);
                LDSM_X4(ahf[0], ahf[1], ahf[2], ahf[3], sbst + OFF_AH + aoff);
                LDSM_X4(alf[0], alf[1], alf[2], alf[3], sbst + OFF_AL + aoff);
                #pragma unroll
                for (int nt = 0; nt < 4; nt++) {
                    mma_bf16(acc[mt][nt], ahf, bh[nt]);
                    mma_bf16(acc[mt][nt], ahf, bl[nt]);
                    mma_bf16(acc[mt][nt], alf, bh[nt]);
                }
            }
        }

        if (more) CP_WAIT1();
        else      CP_WAIT0();
        __syncthreads();
        st = (st + 1 >= NSTAGE) ? 0 : st + 1;
    }

    // -------- epilogue --------
    const int r4 = lane >> 2;
    const int c2 = (lane & 3) * 2;
    #pragma unroll
    for (int mt = 0; mt < 4; mt++) {
        const int rowb = m0 + wm0 + mt * 16 + r4;
        #pragma unroll
        for (int nt = 0; nt < 4; nt++) {
            const int col = n0 + wn0 + nt * 8 + c2;
            float2 bi = *(const float2*)&bias[col];
            float2 tdv;
            if (MODE == 0) tdv = *(const float2*)&td[col];
            #pragma unroll
            for (int half = 0; half < 2; half++) {
                const int rw = rowb + half * 8;
                float2 ax = *(const float2*)&aux[(size_t)(rw - auxOff) * DIM + col];
                float v0 = acc[mt][nt][half * 2 + 0] + bi.x;
                float v1 = acc[mt][nt][half * 2 + 1] + bi.y;
                if (MODE == 0) {
                    float g0 = 1.0f / (1.0f + expf(-v0));
                    float g1 = 1.0f / (1.0f + expf(-v1));
                    float o0 = g0 * ax.x * tdv.x;
                    float o1 = g1 * ax.y * tdv.y;
                    float h0 = __bfloat162float(__float2bfloat16(o0));
                    float h1 = __bfloat162float(__float2bfloat16(o1));
                    *(uint32_t*)&Ch[(size_t)rw * DIM + col] = pack_bf16x2(o0, o1);
                    *(uint32_t*)&Cl[(size_t)rw * DIM + col] = pack_bf16x2(o0 - h0, o1 - h1);
                } else {
                    float2 o = make_float2(v0 + ax.x, v1 + ax.y);
                    *(float2*)&C[(size_t)rw * DIM + col] = o;
                }
            }
        }
    }
}

// ---------------------------------------------------------------------------
// Row LayerNorm over BOTH stacks (grid = 32768 rows).
// rows < TTOK use (g_e, beta_e) -> dst_e[row]; rows >= TTOK use (g_t, beta_t)
// -> dst_t[row - TTOK]. Also emits bf16 hi/lo at global row.
// ---------------------------------------------------------------------------
__global__ __launch_bounds__(256) void ln_kernel(
    const float* __restrict__ Y,
    const float* __restrict__ g_e, const float* __restrict__ beta_e,
    const float* __restrict__ g_t, const float* __restrict__ beta_t,
    float* __restrict__ dst_e, float* __restrict__ dst_t,
    __nv_bfloat16* __restrict__ Oh, __nv_bfloat16* __restrict__ Ol)
{
    const int row = blockIdx.x;
    const int tid = threadIdx.x;
    const int stk = (row >= TTOK);
    const float* g    = stk ? g_t    : g_e;
    const float* beta = stk ? beta_t : beta_e;
    float* O = stk ? (dst_t + (size_t)(row - TTOK) * DIM) : (dst_e + (size_t)row * DIM);

    float4 v = *(const float4*)&Y[(size_t)row * DIM + tid * 4];
    float s  = v.x + v.y + v.z + v.w;
    float ss = v.x * v.x + v.y * v.y + v.z * v.z + v.w * v.w;

    __shared__ float rs[8], rss[8];
    #pragma unroll
    for (int o = 16; o > 0; o >>= 1) {
        s  += __shfl_down_sync(0xffffffffu, s,  o);
        ss += __shfl_down_sync(0xffffffffu, ss, o);
    }
    if ((tid & 31) == 0) { rs[tid >> 5] = s; rss[tid >> 5] = ss; }
    __syncthreads();
    float ts = 0.f, tss = 0.f;
    #pragma unroll
    for (int w = 0; w < 8; w++) { ts += rs[w]; tss += rss[w]; }
    float mu   = ts * (1.0f / DIM);
    float var  = tss * (1.0f / DIM) - mu * mu;
    float rstd = rsqrtf(var + LN_EPS);

    float4 g4 = *(const float4*)&g[tid * 4];
    float4 b4 = *(const float4*)&beta[tid * 4];
    float4 o4;
    o4.x = (v.x - mu) * rstd * g4.x + b4.x;
    o4.y = (v.y - mu) * rstd * g4.y + b4.y;
    o4.z = (v.z - mu) * rstd * g4.z + b4.z;
    o4.w = (v.w - mu) * rstd * g4.w + b4.w;
    *(float4*)&O[tid * 4] = o4;
    const size_t base = (size_t)row * DIM + tid * 4;
    float hx = __bfloat162float(__float2bfloat16(o4.x));
    float hy = __bfloat162float(__float2bfloat16(o4.y));
    float hz = __bfloat162float(__float2bfloat16(o4.z));
    float hw = __bfloat162float(__float2bfloat16(o4.w));
    *(uint2*)&Oh[base] = make_uint2(pack_bf16x2(o4.x, o4.y), pack_bf16x2(o4.z, o4.w));
    *(uint2*)&Ol[base] = make_uint2(pack_bf16x2(o4.x - hx, o4.y - hy),
                                    pack_bf16x2(o4.z - hz, o4.w - hw));
}

// ---------------------------------------------------------------------------
// Gate softmax + top-2 mask
// ---------------------------------------------------------------------------
__global__ __launch_bounds__(128) void gate_kernel(
    const float* __restrict__ Z, const float* __restrict__ W,
    const float* __restrict__ b, float* __restrict__ probs_out,
    int* __restrict__ mask_out)
{
    const int t   = blockIdx.x;
    const int tid = threadIdx.x;
    const float* z = Z + (size_t)t * DIM;
    float4 acc = make_float4(0.f, 0.f, 0.f, 0.f);
    for (int d = tid; d < DIM; d += 128) {
        float zv = z[d];
        float4 w = *(const float4*)&W[d * 4];
        acc.x = fmaf(zv, w.x, acc.x);
        acc.y = fmaf(zv, w.y, acc.y);
        acc.z = fmaf(zv, w.z, acc.z);
        acc.w = fmaf(zv, w.w, acc.w);
    }
    __shared__ float4 red[128];
    red[tid] = acc;
    __syncthreads();
    for (int s = 64; s > 0; s >>= 1) {
        if (tid < s) {
            float4 o = red[tid + s];
            red[tid].x += o.x; red[tid].y += o.y;
            red[tid].z += o.z; red[tid].w += o.w;
        }
        __syncthreads();
    }
    if (tid == 0) {
        float l[4] = { red[0].x + b[0], red[0].y + b[1],
                       red[0].z + b[2], red[0].w + b[3] };
        float mx = l[0];
        #pragma unroll
        for (int e = 1; e < 4; e++) mx = fmaxf(mx, l[e]);
        float ex[4], sum = 0.f;
        #pragma unroll
        for (int e = 0; e < 4; e++) { ex[e] = expf(l[e] - mx); sum += ex[e]; }
        float inv = 1.0f / sum;
        #pragma unroll
        for (int e = 0; e < 4; e++) probs_out[(size_t)t * 4 + e] = ex[e] * inv;
        int i1 = 0;
        #pragma unroll
        for (int e = 1; e < 4; e++) if (l[e] > l[i1]) i1 = e;
        int i2 = -1;
        #pragma unroll
        for (int e = 0; e < 4; e++) {
            if (e == i1) continue;
            if (i2 < 0 || l[e] > l[i2]) i2 = e;
        }
        mask_out[t] = (1 << i1) | (1 << i2);
    }
}

// ---------------------------------------------------------------------------
// H = mask * gelu(Z @ Aflat)
// ---------------------------------------------------------------------------
__global__ __launch_bounds__(256) void h_kernel(
    const float* __restrict__ Z, const float* __restrict__ loraA,
    const int* __restrict__ mask, float* __restrict__ H)
{
    __shared__ float Zs[16][68];
    __shared__ float Afs[16][64];

    const int m0  = blockIdx.x * 64;
    const int tid = threadIdx.x;
    const int ty  = tid >> 4;
    const int tx  = tid & 15;

    float acc[4][4];
    #pragma unroll
    for (int i = 0; i < 4; i++)
        #pragma unroll
        for (int j = 0; j < 4; j++) acc[i][j] = 0.f;

    for (int k0 = 0; k0 < DIM; k0 += 16) {
        {
            int row = tid >> 2;
            int kq  = (tid & 3) << 2;
            float4 v = *(const float4*)&Z[(size_t)(m0 + row) * DIM + k0 + kq];
            Zs[kq + 0][row] = v.x; Zs[kq + 1][row] = v.y;
            Zs[kq + 2][row] = v.z; Zs[kq + 3][row] = v.w;
        }
        {
            int k  = tid >> 4;
            int c4 = (tid & 15) << 2;
            int e  = c4 >> 4;
            int r  = c4 & 15;
            float4 v = *(const float4*)&loraA[(size_t)e * DIM * RANK + (size_t)(k0 + k) * RANK + r];
            *(float4*)&Afs[k][c4] = v;
        }
        __syncthreads();
        #pragma unroll
        for (int k = 0; k < 16; k++) {
            float a[4], b[4];
            *(float4*)&a[0] = *(float4*)&Zs[k][ty * 4];
            *(float4*)&b[0] = *(float4*)&Afs[k][tx * 4];
            #pragma unroll
            for (int i = 0; i < 4; i++)
                #pragma unroll
                for (int j = 0; j < 4; j++)
                    acc[i][j] = fmaf(a[i], b[j], acc[i][j]);
        }
        __syncthreads();
    }

    #pragma unroll
    for (int i = 0; i < 4; i++) {
        int m  = m0 + ty * 4 + i;
        int mk = mask[m];
        #pragma unroll
        for (int j = 0; j < 4; j++) {
            int c = tx * 4 + j;
            int e = c >> 4;
            float x = acc[i][j];
            float h = 0.5f * x * (1.0f + erff(x * 0.70710678118654752f));
            H[(size_t)m * ERCOL + c] = ((mk >> e) & 1) ? h : 0.0f;
        }
    }
}

// ---------------------------------------------------------------------------
// pred = H @ Bflat
// ---------------------------------------------------------------------------
__global__ __launch_bounds__(256) void combine_kernel(
    const float* __restrict__ H, const float* __restrict__ Bf,
    float* __restrict__ O)
{
    const int d  = blockIdx.y * 256 + threadIdx.x;
    const int t0 = blockIdx.x * 16;
    __shared__ float hs[16][64];
    {
        int row = threadIdx.x >> 4;
        int c   = (threadIdx.x & 15) << 2;
        *(float4*)&hs[row][c] = *(const float4*)&H[(size_t)(t0 + row) * ERCOL + c];
    }
    __syncthreads();
    float acc[16];
    #pragma unroll
    for (int i = 0; i < 16; i++) acc[i] = 0.f;
    #pragma unroll 4
    for (int c = 0; c < 64; c++) {
        float bv = Bf[(size_t)c * DIM + d];
        #pragma unroll
        for (int i = 0; i < 16; i++) acc[i] = fmaf(hs[i][c], bv, acc[i]);
    }
    #pragma unroll
    for (int i = 0; i < 16; i++) O[(size_t)(t0 + i) * DIM + d] = acc[i];
}

// ---------------------------------------------------------------------------
extern "C" void kernel_launch(void* const* d_in, const int* in_sizes, int n_in,
                              void* d_out, int out_size)
{
    const float* x_ctx  = (const float*)d_in[0];
    const float* x_tgt  = (const float*)d_in[1];
    const float* P[2][7];
    for (int i = 0; i < 7; i++) { P[0][i] = (const float*)d_in[2 + i];
                                  P[1][i] = (const float*)d_in[9 + i]; }
    const float* gate_W = (const float*)d_in[16];
    const float* gate_b = (const float*)d_in[17];
    const float* lora_A = (const float*)d_in[18];
    const float* lora_B = (const float*)d_in[19];

    float* out      = (float*)d_out;
    float* out_pred = out;
    float* out_gate = out + (size_t)TTOK * DIM;
    float* out_ztgt = out_gate + (size_t)TTOK * NEXP;

    float *bufA, *bufC, *bufH; int* bufM;
    __nv_bfloat16 *Ah, *Al, *Bh, *Bl, *Wh, *Wl;
    cudaGetSymbolAddress((void**)&bufA, g_bufA);
    cudaGetSymbolAddress((void**)&bufC, g_bufC);
    cudaGetSymbolAddress((void**)&bufH, g_H);
    cudaGetSymbolAddress((void**)&Ah,   g_Ah);
    cudaGetSymbolAddress((void**)&Al,   g_Al);
    cudaGetSymbolAddress((void**)&Bh,   g_Bh);
    cudaGetSymbolAddress((void**)&Bl,   g_Bl);
    cudaGetSymbolAddress((void**)&Wh,   g_Wh);
    cudaGetSymbolAddress((void**)&Wl,   g_Wl);
    cudaGetSymbolAddress((void**)&bufM, g_maskbuf);

    cudaFuncSetAttribute(gemm_mma<0>, cudaFuncAttributeMaxDynamicSharedMemorySize, SMEM_TOTAL);
    cudaFuncSetAttribute(gemm_mma<1>, cudaFuncAttributeMaxDynamicSharedMemorySize, SMEM_TOTAL);

    wsplit_all<<<dim3(32, 32, 12), 256>>>(P[0][0], P[0][3], P[1][0], P[1][3], Wh, Wl);

    const int splitGrid = (TTOK * DIM) / 1024;
    split_x<<<splitGrid, 256>>>(x_ctx, Ah, Al);
    split_x<<<splitGrid, 256>>>(x_tgt, Ah + (size_t)TTOK * DIM, Al + (size_t)TTOK * DIM);

    const dim3 gg(DIM / BN, TTOK2 / BM);   // (8, 256) = 2048 CTAs

    for (int l = 0; l < 3; l++) {
        // aux/residual fp32 source, per stack
        const float* aux_e = (l == 0) ? x_ctx : bufA;
        const float* aux_t = (l == 0) ? x_tgt : (bufA + (size_t)TTOK * DIM);
        const int wiE = 0 * 6 + l,     wiT = 1 * 6 + l;
        const int woE = 0 * 6 + 3 + l, woT = 1 * 6 + 3 + l;

        gemm_mma<0><<<gg, 256, SMEM_TOTAL>>>(
            Ah, Al, Wh, Wl, wiE, wiT,
            P[0][1] + l * DIM, P[1][1] + l * DIM,     // bi
            aux_e, aux_t,
            P[0][2] + l * DIM, P[1][2] + l * DIM,     // td
            nullptr, Bh, Bl);

        gemm_mma<1><<<gg, 256, SMEM_TOTAL>>>(
            Bh, Bl, Wh, Wl, woE, woT,
            P[0][4] + l * DIM, P[1][4] + l * DIM,     // bo
            aux_e, aux_t,
            nullptr, nullptr,
            bufC, nullptr, nullptr);

        float* dst_t = (l == 2) ? out_ztgt : (bufA + (size_t)TTOK * DIM);
        ln_kernel<<<TTOK2, 256>>>(
            bufC,
            P[0][5] + l * DIM, P[0][6] + l * DIM,
            P[1][5] + l * DIM, P[1][6] + l * DIM,
            bufA, dst_t, Ah, Al);
    }

    gate_kernel<<<TTOK, 128>>>(bufA, gate_W, gate_b, out_gate, bufM);
    h_kernel<<<TTOK / 64, 256>>>(bufA, lora_A, bufM, bufH);
    combine_kernel<<<dim3(TTOK / 16, DIM / 256), 256>>>(bufH, lora_B, out_pred);
}